// round 10
// baseline (speedup 1.0000x reference)
#include <cuda_runtime.h>
#include <cuda_fp16.h>
#include <math.h>
#include <stdint.h>

#define N_ROWS      4096
#define NUM_CLASSES 751
#define D_FEAT      2048
#define MARGIN1     0.5f
#define NTILE       32
#define NBLOCKS_TRI 528
#define KC          64                    // halfs per k-chunk (128 B/row)
#define CHUNKS      (D_FEAT / KC)         // 32
#define STAGES      3
#define LDH         72                    // padded smem row stride (halfs)
#define STAGE_HALFS (128 * LDH)           // 9216
#define STAGE_BYTES (STAGE_HALFS * 2)     // 18432
#define SMEM_BYTES  (2 * STAGES * STAGE_BYTES)  // 110592
#define LREG        24                    // ceil(751/32)

// ---------------- device scratch ---------------------------------------------
__device__ __half   g_feat_h[(size_t)N_ROWS * D_FEAT];
__device__ float    g_sq[N_ROWS];
__device__ float    g_xrow[N_ROWS];
__device__ unsigned g_min_an[N_ROWS];
__device__ unsigned g_max_ap[N_ROWS];
__device__ unsigned g_done = 0;           // wraps 527 -> 0 each launch

// ---------------- PTX helpers -------------------------------------------------
__device__ __forceinline__ uint32_t smem_u32(const void* p) {
    uint32_t a;
    asm("{ .reg .u64 t; cvta.to.shared.u64 t, %1; cvt.u32.u64 %0, t; }"
        : "=r"(a) : "l"(p));
    return a;
}
__device__ __forceinline__ void cpasync16(uint32_t dst, const void* src) {
    asm volatile("cp.async.cg.shared.global [%0], [%1], 16;" :: "r"(dst), "l"(src));
}
__device__ __forceinline__ void ldmx4(uint32_t* r, uint32_t addr) {
    asm volatile("ldmatrix.sync.aligned.m8n8.x4.shared.b16 {%0,%1,%2,%3}, [%4];"
                 : "=r"(r[0]), "=r"(r[1]), "=r"(r[2]), "=r"(r[3]) : "r"(addr));
}
__device__ __forceinline__ void mma_f16_16x8x16(float* c, const uint32_t* a,
                                                const uint32_t* b) {
    asm volatile(
        "mma.sync.aligned.m16n8k16.row.col.f32.f16.f16.f32 "
        "{%0,%1,%2,%3}, {%4,%5,%6,%7}, {%8,%9}, {%0,%1,%2,%3};"
        : "+f"(c[0]), "+f"(c[1]), "+f"(c[2]), "+f"(c[3])
        : "r"(a[0]), "r"(a[1]), "r"(a[2]), "r"(a[3]), "r"(b[0]), "r"(b[1]));
}

// ---------------- block reduce (blockDim.x == 256) -----------------------------
__device__ __forceinline__ float blockReduceSum(float v) {
    __shared__ float red[8];
    __shared__ float bc;
    int lane = threadIdx.x & 31, wid = threadIdx.x >> 5;
    #pragma unroll
    for (int s = 16; s; s >>= 1) v += __shfl_xor_sync(0xffffffffu, v, s);
    if (lane == 0) red[wid] = v;
    __syncthreads();
    if (threadIdx.x == 0) {
        float r = 0.f;
        #pragma unroll
        for (int w = 0; w < 8; ++w) r += red[w];
        bc = r;
    }
    __syncthreads();
    return bc;
}

// ---------------- fused prep: sq + fp16 convert + xent + init ------------------
// 2 warps per row: grid 1024 x 256 (8 warps -> 4 rows)
__global__ void prep_kernel(const float* __restrict__ feat,
                            const float* __restrict__ logits,
                            const int*   __restrict__ targets) {
    const int tid  = threadIdx.x;
    const int lane = tid & 31;
    const int wid  = tid >> 5;
    const int rloc = wid >> 1;             // 0..3 row within block
    const int half = wid & 1;              // which half of the row
    const int row  = blockIdx.x * 4 + rloc;

    // ---- sq + convert: this warp handles 1024 floats (8 float4 per lane) ----
    const float4* f = reinterpret_cast<const float4*>(feat + (size_t)row * D_FEAT)
                      + half * 256;
    uint2* o = reinterpret_cast<uint2*>(g_feat_h + (size_t)row * D_FEAT) + half * 256;
    float s0 = 0.f, s1 = 0.f, s2 = 0.f, s3 = 0.f;
    #pragma unroll
    for (int it = 0; it < 2; ++it) {
        float4 v0 = f[lane + (it * 4 + 0) * 32];
        float4 v1 = f[lane + (it * 4 + 1) * 32];
        float4 v2 = f[lane + (it * 4 + 2) * 32];
        float4 v3 = f[lane + (it * 4 + 3) * 32];
        __half2 a0 = __floats2half2_rn(v0.x, v0.y), a1 = __floats2half2_rn(v0.z, v0.w);
        __half2 b0 = __floats2half2_rn(v1.x, v1.y), b1 = __floats2half2_rn(v1.z, v1.w);
        __half2 c0 = __floats2half2_rn(v2.x, v2.y), c1 = __floats2half2_rn(v2.z, v2.w);
        __half2 d0 = __floats2half2_rn(v3.x, v3.y), d1 = __floats2half2_rn(v3.z, v3.w);
        float2 ra0 = __half22float2(a0), ra1 = __half22float2(a1);
        float2 rb0 = __half22float2(b0), rb1 = __half22float2(b1);
        float2 rc0 = __half22float2(c0), rc1 = __half22float2(c1);
        float2 rd0 = __half22float2(d0), rd1 = __half22float2(d1);
        s0 += ra0.x * ra0.x + ra0.y * ra0.y + ra1.x * ra1.x + ra1.y * ra1.y;
        s1 += rb0.x * rb0.x + rb0.y * rb0.y + rb1.x * rb1.x + rb1.y * rb1.y;
        s2 += rc0.x * rc0.x + rc0.y * rc0.y + rc1.x * rc1.x + rc1.y * rc1.y;
        s3 += rd0.x * rd0.x + rd0.y * rd0.y + rd1.x * rd1.x + rd1.y * rd1.y;
        uint2 w;
        w.x = *reinterpret_cast<uint32_t*>(&a0); w.y = *reinterpret_cast<uint32_t*>(&a1);
        o[lane + (it * 4 + 0) * 32] = w;
        w.x = *reinterpret_cast<uint32_t*>(&b0); w.y = *reinterpret_cast<uint32_t*>(&b1);
        o[lane + (it * 4 + 1) * 32] = w;
        w.x = *reinterpret_cast<uint32_t*>(&c0); w.y = *reinterpret_cast<uint32_t*>(&c1);
        o[lane + (it * 4 + 2) * 32] = w;
        w.x = *reinterpret_cast<uint32_t*>(&d0); w.y = *reinterpret_cast<uint32_t*>(&d1);
        o[lane + (it * 4 + 3) * 32] = w;
    }
    float s = (s0 + s1) + (s2 + s3);
    #pragma unroll
    for (int sft = 16; sft; sft >>= 1) s += __shfl_xor_sync(0xffffffffu, s, sft);

    __shared__ float sqp[8];
    if (lane == 0) sqp[wid] = s;

    // ---- xent on the half==0 warp of each row (regs-resident logits) ----
    float xe = 0.f;
    if (half == 0) {
        const float* lr = logits + (size_t)row * NUM_CLASSES;
        float lv[LREG];
        #pragma unroll
        for (int k = 0; k < LREG; ++k) {
            const int c = lane + k * 32;
            lv[k] = (c < NUM_CLASSES) ? lr[c] : -1e30f;
        }
        float m = -1e30f;
        #pragma unroll
        for (int k = 0; k < LREG; ++k) m = fmaxf(m, lv[k]);
        #pragma unroll
        for (int sft = 16; sft; sft >>= 1)
            m = fmaxf(m, __shfl_xor_sync(0xffffffffu, m, sft));
        float es = 0.f;
        #pragma unroll
        for (int k = 0; k < LREG; ++k) {
            const int c = lane + k * 32;
            es += (c < NUM_CLASSES) ? expf(lv[k] - m) : 0.f;
        }
        #pragma unroll
        for (int sft = 16; sft; sft >>= 1)
            es += __shfl_xor_sync(0xffffffffu, es, sft);
        xe = m + logf(es) - lr[targets[row]];
    }

    __syncthreads();
    if (half == 0 && lane == 0) {
        g_sq[row]     = sqp[2 * rloc] + sqp[2 * rloc + 1];
        g_xrow[row]   = xe;
        g_min_an[row] = 0x7F800000u;
        g_max_ap[row] = 0u;
    }
}

// ---------------- fp16 HMMA Gram GEMM + mining + fused finalize ----------------
__global__ __launch_bounds__(256, 2) void gemm_mine_hmma(float* __restrict__ out) {
    extern __shared__ __half sm[];
    const int tid  = threadIdx.x;
    const int lane = tid & 31;
    const int wid  = tid >> 5;
    const int wm   = wid >> 1;       // 0..3
    const int wn   = wid & 1;        // 0..1
    const int grp  = lane >> 2;      // 0..7
    const int tig  = lane & 3;       // 0..3

    int t = blockIdx.x, a = 0;
    while (t >= NTILE - a) { t -= NTILE - a; ++a; }
    const int b = a + t;
    const bool diag = (a == b);
    const int i0 = a * 128, j0 = b * 128;

    const int rw = tid >> 3;
    const int q  = tid & 7;
    const __half* pA = g_feat_h + (size_t)(i0 + rw) * D_FEAT + q * 8;
    const __half* pB = g_feat_h + (size_t)(j0 + rw) * D_FEAT + q * 8;
    const uint32_t base = smem_u32(sm);
    const uint32_t ldst = (uint32_t)(rw * LDH + q * 8) * 2;
    const uint32_t smA = base, smB = base + STAGES * STAGE_BYTES;

    const uint32_t aoff = (uint32_t)((wm * 32 + (lane & 15)) * LDH
                                     + ((lane >> 4) << 3)) * 2;
    const uint32_t boff = (uint32_t)((wn * 64 + ((lane >> 4) << 3) + (lane & 7)) * LDH
                                     + (((lane >> 3) & 1) << 3)) * 2;

    auto load_chunk = [&](int s, int c) {
        const __half* aa = pA + c * KC;
        const __half* bb = pB + c * KC;
        const uint32_t da = smA + s * STAGE_BYTES + ldst;
        const uint32_t db = smB + s * STAGE_BYTES + ldst;
        #pragma unroll
        for (int u = 0; u < 4; ++u) {
            cpasync16(da + u * (32 * LDH * 2), aa + (size_t)(u * 32) * D_FEAT);
            cpasync16(db + u * (32 * LDH * 2), bb + (size_t)(u * 32) * D_FEAT);
        }
        asm volatile("cp.async.commit_group;" ::: "memory");
    };

    float acc[2][8][4];
    #pragma unroll
    for (int mf = 0; mf < 2; ++mf)
        #pragma unroll
        for (int nf = 0; nf < 8; ++nf)
            #pragma unroll
            for (int r = 0; r < 4; ++r) acc[mf][nf][r] = 0.f;

    load_chunk(0, 0);
    load_chunk(1, 1);

    for (int c = 0; c < CHUNKS; ++c) {
        const int s = c % STAGES;
        asm volatile("cp.async.wait_group 1;" ::: "memory");
        __syncthreads();
        if (c + STAGES - 1 < CHUNKS)
            load_chunk((c + STAGES - 1) % STAGES, c + STAGES - 1);

        const uint32_t As = smA + s * STAGE_BYTES + aoff;
        const uint32_t Bs = smB + s * STAGE_BYTES + boff;

        #pragma unroll
        for (int k16 = 0; k16 < 4; ++k16) {
            const uint32_t kb = k16 * 32;   // 16 halfs
            uint32_t av[2][4], bv[8][2];
            ldmx4(av[0], As + kb);
            ldmx4(av[1], As + kb + 16 * LDH * 2);
            #pragma unroll
            for (int p = 0; p < 4; ++p) {
                uint32_t r[4];
                ldmx4(r, Bs + kb + p * (16 * LDH * 2));
                bv[2 * p][0]     = r[0];
                bv[2 * p][1]     = r[1];
                bv[2 * p + 1][0] = r[2];
                bv[2 * p + 1][1] = r[3];
            }
            #pragma unroll
            for (int mf = 0; mf < 2; ++mf)
                #pragma unroll
                for (int nf = 0; nf < 8; ++nf)
                    mma_f16_16x8x16(acc[mf][nf], av[mf], bv[nf]);
        }
    }

    // ---------------- epilogue: d^2 + batch-hard mining ----------------------
    __syncthreads();
    unsigned* rminS = (unsigned*)sm;
    unsigned* rmaxS = rminS + 128;
    unsigned* cminS = rminS + 256;
    if (tid < 128) {
        rminS[tid] = 0x7F800000u;
        rmaxS[tid] = 0u;
        cminS[tid] = 0x7F800000u;
    }
    __syncthreads();

    const int ib = i0 + wm * 32 + grp;
    const int jb = j0 + wn * 64 + 2 * tig;

    float sqj[8][2];
    #pragma unroll
    for (int nf = 0; nf < 8; ++nf) {
        sqj[nf][0] = __ldg(&g_sq[jb + nf * 8]);
        sqj[nf][1] = __ldg(&g_sq[jb + nf * 8 + 1]);
    }

    float cl[8][2];
    #pragma unroll
    for (int nf = 0; nf < 8; ++nf) { cl[nf][0] = 1e30f; cl[nf][1] = 1e30f; }

    #pragma unroll
    for (int mf = 0; mf < 2; ++mf) {
        const int iA = ib + mf * 16, iB = iA + 8;
        const float sq0 = __ldg(&g_sq[iA]);
        const float sq1 = __ldg(&g_sq[iB]);
        float rm0 = 1e30f, rm1 = 1e30f, rx0 = 0.f, rx1 = 0.f;
        #pragma unroll
        for (int nf = 0; nf < 8; ++nf) {
            #pragma unroll
            for (int p = 0; p < 2; ++p) {
                const int j = jb + nf * 8 + p;
                float d0 = fmaxf(sq0 + sqj[nf][p] - 2.f * acc[mf][nf][p],     0.f);
                float d1 = fmaxf(sq1 + sqj[nf][p] - 2.f * acc[mf][nf][2 + p], 0.f);
                if (diag) {
                    bool s0 = (iA >> 2) == (j >> 2);
                    bool s1 = (iB >> 2) == (j >> 2);
                    if (s0) rx0 = fmaxf(rx0, d0); else rm0 = fminf(rm0, d0);
                    if (s1) rx1 = fmaxf(rx1, d1); else rm1 = fminf(rm1, d1);
                } else {
                    rm0 = fminf(rm0, d0);
                    rm1 = fminf(rm1, d1);
                    cl[nf][p] = fminf(cl[nf][p], fminf(d0, d1));
                }
            }
        }
        #pragma unroll
        for (int sft = 1; sft <= 2; sft <<= 1) {
            rm0 = fminf(rm0, __shfl_xor_sync(0xffffffffu, rm0, sft));
            rm1 = fminf(rm1, __shfl_xor_sync(0xffffffffu, rm1, sft));
            rx0 = fmaxf(rx0, __shfl_xor_sync(0xffffffffu, rx0, sft));
            rx1 = fmaxf(rx1, __shfl_xor_sync(0xffffffffu, rx1, sft));
        }
        if (tig == 0) {
            atomicMin(&rminS[iA - i0], __float_as_uint(rm0));
            atomicMin(&rminS[iB - i0], __float_as_uint(rm1));
            if (diag) {
                atomicMax(&rmaxS[iA - i0], __float_as_uint(rx0));
                atomicMax(&rmaxS[iB - i0], __float_as_uint(rx1));
            }
        }
    }

    if (!diag) {
        #pragma unroll
        for (int nf = 0; nf < 8; ++nf)
            #pragma unroll
            for (int p = 0; p < 2; ++p) {
                float v = cl[nf][p];
                #pragma unroll
                for (int sft = 4; sft <= 16; sft <<= 1)
                    v = fminf(v, __shfl_xor_sync(0xffffffffu, v, sft));
                if (grp == 0)
                    atomicMin(&cminS[wn * 64 + nf * 8 + 2 * tig + p],
                              __float_as_uint(v));
            }
    }

    __syncthreads();
    if (tid < 128) {
        atomicMin(&g_min_an[i0 + tid], rminS[tid]);
        if (diag) atomicMax(&g_max_ap[i0 + tid], rmaxS[tid]);
        else      atomicMin(&g_min_an[j0 + tid], cminS[tid]);
    }

    // ---------------- finalize in the last-arriving CTA ----------------------
    __threadfence();
    __syncthreads();
    __shared__ unsigned s_last;
    if (tid == 0)
        s_last = (atomicInc(&g_done, NBLOCKS_TRI - 1) == NBLOCKS_TRI - 1) ? 1u : 0u;
    __syncthreads();
    if (s_last) {
        __threadfence();   // acquire
        float acc2 = 0.f;
        #pragma unroll
        for (int it = 0; it < N_ROWS / 256; ++it) {
            const int i = it * 256 + tid;
            float ap = sqrtf(fmaxf(__uint_as_float(g_max_ap[i]), 1e-12f));
            float an = sqrtf(fmaxf(__uint_as_float(g_min_an[i]), 1e-12f));
            acc2 += g_xrow[i] + fmaxf(ap - an + MARGIN1, 0.f);
        }
        float tot = blockReduceSum(acc2);
        if (tid == 0) out[0] = tot / (float)N_ROWS;
    }
}

// ---------------- launch --------------------------------------------------------
extern "C" void kernel_launch(void* const* d_in, const int* in_sizes, int n_in,
                              void* d_out, int out_size) {
    const float* logits  = (const float*)d_in[0];
    const float* feat    = (const float*)d_in[1];
    const int*   targets = (const int*)d_in[2];
    float* out = (float*)d_out;

    cudaFuncSetAttribute(gemm_mine_hmma,
                         cudaFuncAttributeMaxDynamicSharedMemorySize, SMEM_BYTES);

    prep_kernel<<<1024, 256>>>(feat, logits, targets);
    gemm_mine_hmma<<<NBLOCKS_TRI, 256, SMEM_BYTES>>>(out);
}

// round 11
// speedup vs baseline: 1.0681x; 1.0681x over previous
#include <cuda_runtime.h>
#include <cuda_fp16.h>
#include <math.h>
#include <stdint.h>

#define N_ROWS      4096
#define NUM_CLASSES 751
#define D_FEAT      2048
#define MARGIN1     0.5f
#define NTILE       32
#define NBLOCKS_TRI 528
#define KC          64                    // halfs per k-chunk (128 B/row)
#define CHUNKS      (D_FEAT / KC)         // 32
#define STAGES      3
#define LDH         72                    // padded smem row stride (halfs)
#define STAGE_HALFS (128 * LDH)           // 9216
#define STAGE_BYTES (STAGE_HALFS * 2)     // 18432
#define SMEM_BYTES  (2 * STAGES * STAGE_BYTES)  // 110592
#define FIN_BLOCKS  16
#define LREG        24                    // ceil(751/32)

// ---------------- device scratch ---------------------------------------------
__device__ __half   g_feat_h[(size_t)N_ROWS * D_FEAT];
__device__ float    g_sq[N_ROWS];
__device__ float    g_xrow[N_ROWS];
__device__ unsigned g_min_an[N_ROWS];
__device__ unsigned g_max_ap[N_ROWS];
__device__ float    g_acc;
__device__ unsigned g_done = 0;           // wraps FIN_BLOCKS-1 -> 0 each launch

// ---------------- PTX helpers -------------------------------------------------
__device__ __forceinline__ uint32_t smem_u32(const void* p) {
    uint32_t a;
    asm("{ .reg .u64 t; cvta.to.shared.u64 t, %1; cvt.u32.u64 %0, t; }"
        : "=r"(a) : "l"(p));
    return a;
}
__device__ __forceinline__ void cpasync16(uint32_t dst, const void* src) {
    asm volatile("cp.async.cg.shared.global [%0], [%1], 16;" :: "r"(dst), "l"(src));
}
__device__ __forceinline__ void ldmx4(uint32_t* r, uint32_t addr) {
    asm volatile("ldmatrix.sync.aligned.m8n8.x4.shared.b16 {%0,%1,%2,%3}, [%4];"
                 : "=r"(r[0]), "=r"(r[1]), "=r"(r[2]), "=r"(r[3]) : "r"(addr));
}
__device__ __forceinline__ void mma_f16_16x8x16(float* c, const uint32_t* a,
                                                const uint32_t* b) {
    asm volatile(
        "mma.sync.aligned.m16n8k16.row.col.f32.f16.f16.f32 "
        "{%0,%1,%2,%3}, {%4,%5,%6,%7}, {%8,%9}, {%0,%1,%2,%3};"
        : "+f"(c[0]), "+f"(c[1]), "+f"(c[2]), "+f"(c[3])
        : "r"(a[0]), "r"(a[1]), "r"(a[2]), "r"(a[3]), "r"(b[0]), "r"(b[1]));
}

// ---------------- block reduce (blockDim.x == 256) -----------------------------
__device__ __forceinline__ float blockReduceSum(float v) {
    __shared__ float red[8];
    __shared__ float bc;
    int lane = threadIdx.x & 31, wid = threadIdx.x >> 5;
    #pragma unroll
    for (int s = 16; s; s >>= 1) v += __shfl_xor_sync(0xffffffffu, v, s);
    if (lane == 0) red[wid] = v;
    __syncthreads();
    if (threadIdx.x == 0) {
        float r = 0.f;
        #pragma unroll
        for (int w = 0; w < 8; ++w) r += red[w];
        bc = r;
    }
    __syncthreads();
    return bc;
}

// ---------------- fused prep: sq + fp16 convert + xent + init ------------------
// 2 warps per row: grid 1024 x 256 (8 warps -> 4 rows)
__global__ void prep_kernel(const float* __restrict__ feat,
                            const float* __restrict__ logits,
                            const int*   __restrict__ targets) {
    const int tid  = threadIdx.x;
    const int lane = tid & 31;
    const int wid  = tid >> 5;
    const int rloc = wid >> 1;             // 0..3 row within block
    const int half = wid & 1;              // which half of the row
    const int row  = blockIdx.x * 4 + rloc;

    // ---- sq + convert: this warp handles 1024 floats (8 float4 per lane) ----
    const float4* f = reinterpret_cast<const float4*>(feat + (size_t)row * D_FEAT)
                      + half * 256;
    uint2* o = reinterpret_cast<uint2*>(g_feat_h + (size_t)row * D_FEAT) + half * 256;
    float s0 = 0.f, s1 = 0.f, s2 = 0.f, s3 = 0.f;
    #pragma unroll
    for (int it = 0; it < 2; ++it) {
        float4 v0 = f[lane + (it * 4 + 0) * 32];
        float4 v1 = f[lane + (it * 4 + 1) * 32];
        float4 v2 = f[lane + (it * 4 + 2) * 32];
        float4 v3 = f[lane + (it * 4 + 3) * 32];
        __half2 a0 = __floats2half2_rn(v0.x, v0.y), a1 = __floats2half2_rn(v0.z, v0.w);
        __half2 b0 = __floats2half2_rn(v1.x, v1.y), b1 = __floats2half2_rn(v1.z, v1.w);
        __half2 c0 = __floats2half2_rn(v2.x, v2.y), c1 = __floats2half2_rn(v2.z, v2.w);
        __half2 d0 = __floats2half2_rn(v3.x, v3.y), d1 = __floats2half2_rn(v3.z, v3.w);
        float2 ra0 = __half22float2(a0), ra1 = __half22float2(a1);
        float2 rb0 = __half22float2(b0), rb1 = __half22float2(b1);
        float2 rc0 = __half22float2(c0), rc1 = __half22float2(c1);
        float2 rd0 = __half22float2(d0), rd1 = __half22float2(d1);
        s0 += ra0.x * ra0.x + ra0.y * ra0.y + ra1.x * ra1.x + ra1.y * ra1.y;
        s1 += rb0.x * rb0.x + rb0.y * rb0.y + rb1.x * rb1.x + rb1.y * rb1.y;
        s2 += rc0.x * rc0.x + rc0.y * rc0.y + rc1.x * rc1.x + rc1.y * rc1.y;
        s3 += rd0.x * rd0.x + rd0.y * rd0.y + rd1.x * rd1.x + rd1.y * rd1.y;
        uint2 w;
        w.x = *reinterpret_cast<uint32_t*>(&a0); w.y = *reinterpret_cast<uint32_t*>(&a1);
        o[lane + (it * 4 + 0) * 32] = w;
        w.x = *reinterpret_cast<uint32_t*>(&b0); w.y = *reinterpret_cast<uint32_t*>(&b1);
        o[lane + (it * 4 + 1) * 32] = w;
        w.x = *reinterpret_cast<uint32_t*>(&c0); w.y = *reinterpret_cast<uint32_t*>(&c1);
        o[lane + (it * 4 + 2) * 32] = w;
        w.x = *reinterpret_cast<uint32_t*>(&d0); w.y = *reinterpret_cast<uint32_t*>(&d1);
        o[lane + (it * 4 + 3) * 32] = w;
    }
    float s = (s0 + s1) + (s2 + s3);
    #pragma unroll
    for (int sft = 16; sft; sft >>= 1) s += __shfl_xor_sync(0xffffffffu, s, sft);

    __shared__ float sqp[8];
    if (lane == 0) sqp[wid] = s;

    // ---- xent on the half==0 warp of each row (regs-resident logits) ----
    float xe = 0.f;
    if (half == 0) {
        const float* lr = logits + (size_t)row * NUM_CLASSES;
        float lv[LREG];
        #pragma unroll
        for (int k = 0; k < LREG; ++k) {
            const int c = lane + k * 32;
            lv[k] = (c < NUM_CLASSES) ? lr[c] : -1e30f;
        }
        float m = -1e30f;
        #pragma unroll
        for (int k = 0; k < LREG; ++k) m = fmaxf(m, lv[k]);
        #pragma unroll
        for (int sft = 16; sft; sft >>= 1)
            m = fmaxf(m, __shfl_xor_sync(0xffffffffu, m, sft));
        float es = 0.f;
        #pragma unroll
        for (int k = 0; k < LREG; ++k) {
            const int c = lane + k * 32;
            es += (c < NUM_CLASSES) ? expf(lv[k] - m) : 0.f;
        }
        #pragma unroll
        for (int sft = 16; sft; sft >>= 1)
            es += __shfl_xor_sync(0xffffffffu, es, sft);
        xe = m + logf(es) - lr[targets[row]];
    }

    __syncthreads();
    if (half == 0 && lane == 0) {
        g_sq[row]     = sqp[2 * rloc] + sqp[2 * rloc + 1];
        g_xrow[row]   = xe;
        g_min_an[row] = 0x7F800000u;
        g_max_ap[row] = 0u;
        if (row == 0) g_acc = 0.f;
    }
}

// ---------------- fp16 HMMA Gram GEMM + batch-hard mining ---------------------
__global__ __launch_bounds__(256, 2) void gemm_mine_hmma() {
    extern __shared__ __half sm[];
    const int tid  = threadIdx.x;
    const int lane = tid & 31;
    const int wid  = tid >> 5;
    const int wm   = wid >> 1;       // 0..3
    const int wn   = wid & 1;        // 0..1
    const int grp  = lane >> 2;      // 0..7
    const int tig  = lane & 3;       // 0..3

    int t = blockIdx.x, a = 0;
    while (t >= NTILE - a) { t -= NTILE - a; ++a; }
    const int b = a + t;
    const bool diag = (a == b);
    const int i0 = a * 128, j0 = b * 128;

    const int rw = tid >> 3;
    const int q  = tid & 7;
    const __half* pA = g_feat_h + (size_t)(i0 + rw) * D_FEAT + q * 8;
    const __half* pB = g_feat_h + (size_t)(j0 + rw) * D_FEAT + q * 8;
    const uint32_t base = smem_u32(sm);
    const uint32_t ldst = (uint32_t)(rw * LDH + q * 8) * 2;
    const uint32_t smA = base, smB = base + STAGES * STAGE_BYTES;

    const uint32_t aoff = (uint32_t)((wm * 32 + (lane & 15)) * LDH
                                     + ((lane >> 4) << 3)) * 2;
    const uint32_t boff = (uint32_t)((wn * 64 + ((lane >> 4) << 3) + (lane & 7)) * LDH
                                     + (((lane >> 3) & 1) << 3)) * 2;

    auto load_chunk = [&](int s, int c) {
        const __half* aa = pA + c * KC;
        const __half* bb = pB + c * KC;
        const uint32_t da = smA + s * STAGE_BYTES + ldst;
        const uint32_t db = smB + s * STAGE_BYTES + ldst;
        #pragma unroll
        for (int u = 0; u < 4; ++u) {
            cpasync16(da + u * (32 * LDH * 2), aa + (size_t)(u * 32) * D_FEAT);
            cpasync16(db + u * (32 * LDH * 2), bb + (size_t)(u * 32) * D_FEAT);
        }
        asm volatile("cp.async.commit_group;" ::: "memory");
    };

    float acc[2][8][4];
    #pragma unroll
    for (int mf = 0; mf < 2; ++mf)
        #pragma unroll
        for (int nf = 0; nf < 8; ++nf)
            #pragma unroll
            for (int r = 0; r < 4; ++r) acc[mf][nf][r] = 0.f;

    load_chunk(0, 0);
    load_chunk(1, 1);

    for (int c = 0; c < CHUNKS; ++c) {
        const int s = c % STAGES;
        asm volatile("cp.async.wait_group 1;" ::: "memory");
        __syncthreads();
        if (c + STAGES - 1 < CHUNKS)
            load_chunk((c + STAGES - 1) % STAGES, c + STAGES - 1);

        const uint32_t As = smA + s * STAGE_BYTES + aoff;
        const uint32_t Bs = smB + s * STAGE_BYTES + boff;

        #pragma unroll
        for (int k16 = 0; k16 < 4; ++k16) {
            const uint32_t kb = k16 * 32;   // 16 halfs
            uint32_t av[2][4], bv[8][2];
            ldmx4(av[0], As + kb);
            ldmx4(av[1], As + kb + 16 * LDH * 2);
            #pragma unroll
            for (int p = 0; p < 4; ++p) {
                uint32_t r[4];
                ldmx4(r, Bs + kb + p * (16 * LDH * 2));
                bv[2 * p][0]     = r[0];
                bv[2 * p][1]     = r[1];
                bv[2 * p + 1][0] = r[2];
                bv[2 * p + 1][1] = r[3];
            }
            #pragma unroll
            for (int mf = 0; mf < 2; ++mf)
                #pragma unroll
                for (int nf = 0; nf < 8; ++nf)
                    mma_f16_16x8x16(acc[mf][nf], av[mf], bv[nf]);
        }
    }

    // ---------------- epilogue: d^2 + batch-hard mining ----------------------
    __syncthreads();
    unsigned* rminS = (unsigned*)sm;
    unsigned* rmaxS = rminS + 128;
    unsigned* cminS = rminS + 256;
    if (tid < 128) {
        rminS[tid] = 0x7F800000u;
        rmaxS[tid] = 0u;
        cminS[tid] = 0x7F800000u;
    }
    __syncthreads();

    const int ib = i0 + wm * 32 + grp;
    const int jb = j0 + wn * 64 + 2 * tig;

    float sqj[8][2];
    #pragma unroll
    for (int nf = 0; nf < 8; ++nf) {
        sqj[nf][0] = __ldg(&g_sq[jb + nf * 8]);
        sqj[nf][1] = __ldg(&g_sq[jb + nf * 8 + 1]);
    }

    float cl[8][2];
    #pragma unroll
    for (int nf = 0; nf < 8; ++nf) { cl[nf][0] = 1e30f; cl[nf][1] = 1e30f; }

    #pragma unroll
    for (int mf = 0; mf < 2; ++mf) {
        const int iA = ib + mf * 16, iB = iA + 8;
        const float sq0 = __ldg(&g_sq[iA]);
        const float sq1 = __ldg(&g_sq[iB]);
        float rm0 = 1e30f, rm1 = 1e30f, rx0 = 0.f, rx1 = 0.f;
        #pragma unroll
        for (int nf = 0; nf < 8; ++nf) {
            #pragma unroll
            for (int p = 0; p < 2; ++p) {
                const int j = jb + nf * 8 + p;
                float d0 = fmaxf(sq0 + sqj[nf][p] - 2.f * acc[mf][nf][p],     0.f);
                float d1 = fmaxf(sq1 + sqj[nf][p] - 2.f * acc[mf][nf][2 + p], 0.f);
                if (diag) {
                    bool s0 = (iA >> 2) == (j >> 2);
                    bool s1 = (iB >> 2) == (j >> 2);
                    if (s0) rx0 = fmaxf(rx0, d0); else rm0 = fminf(rm0, d0);
                    if (s1) rx1 = fmaxf(rx1, d1); else rm1 = fminf(rm1, d1);
                } else {
                    rm0 = fminf(rm0, d0);
                    rm1 = fminf(rm1, d1);
                    cl[nf][p] = fminf(cl[nf][p], fminf(d0, d1));
                }
            }
        }
        #pragma unroll
        for (int sft = 1; sft <= 2; sft <<= 1) {
            rm0 = fminf(rm0, __shfl_xor_sync(0xffffffffu, rm0, sft));
            rm1 = fminf(rm1, __shfl_xor_sync(0xffffffffu, rm1, sft));
            rx0 = fmaxf(rx0, __shfl_xor_sync(0xffffffffu, rx0, sft));
            rx1 = fmaxf(rx1, __shfl_xor_sync(0xffffffffu, rx1, sft));
        }
        if (tig == 0) {
            atomicMin(&rminS[iA - i0], __float_as_uint(rm0));
            atomicMin(&rminS[iB - i0], __float_as_uint(rm1));
            if (diag) {
                atomicMax(&rmaxS[iA - i0], __float_as_uint(rx0));
                atomicMax(&rmaxS[iB - i0], __float_as_uint(rx1));
            }
        }
    }

    if (!diag) {
        #pragma unroll
        for (int nf = 0; nf < 8; ++nf)
            #pragma unroll
            for (int p = 0; p < 2; ++p) {
                float v = cl[nf][p];
                #pragma unroll
                for (int sft = 4; sft <= 16; sft <<= 1)
                    v = fminf(v, __shfl_xor_sync(0xffffffffu, v, sft));
                if (grp == 0)
                    atomicMin(&cminS[wn * 64 + nf * 8 + 2 * tig + p],
                              __float_as_uint(v));
            }
    }

    __syncthreads();
    if (tid < 128) {
        atomicMin(&g_min_an[i0 + tid], rminS[tid]);
        if (diag) atomicMax(&g_max_ap[i0 + tid], rmaxS[tid]);
        else      atomicMin(&g_min_an[j0 + tid], cminS[tid]);
    }
}

// ---------------- final scalar (parallel, last-block-writes) -------------------
__global__ void finalize_kernel(float* __restrict__ out) {
    const int i = blockIdx.x * 256 + threadIdx.x;
    float xs = g_xrow[i];
    float ap = sqrtf(fmaxf(__uint_as_float(g_max_ap[i]), 1e-12f));
    float an = sqrtf(fmaxf(__uint_as_float(g_min_an[i]), 1e-12f));
    float tot = blockReduceSum(xs + fmaxf(ap - an + MARGIN1, 0.f));
    if (threadIdx.x == 0) {
        atomicAdd(&g_acc, tot);
        __threadfence();
        unsigned old = atomicInc(&g_done, FIN_BLOCKS - 1);
        if (old == FIN_BLOCKS - 1)
            out[0] = g_acc / (float)N_ROWS;
    }
}

// ---------------- launch --------------------------------------------------------
extern "C" void kernel_launch(void* const* d_in, const int* in_sizes, int n_in,
                              void* d_out, int out_size) {
    const float* logits  = (const float*)d_in[0];
    const float* feat    = (const float*)d_in[1];
    const int*   targets = (const int*)d_in[2];
    float* out = (float*)d_out;

    cudaFuncSetAttribute(gemm_mine_hmma,
                         cudaFuncAttributeMaxDynamicSharedMemorySize, SMEM_BYTES);

    prep_kernel<<<1024, 256>>>(feat, logits, targets);
    gemm_mine_hmma<<<NBLOCKS_TRI, 256, SMEM_BYTES>>>();
    finalize_kernel<<<FIN_BLOCKS, 256>>>(out);
}

// round 12
// speedup vs baseline: 1.0749x; 1.0063x over previous
#include <cuda_runtime.h>
#include <cuda_fp16.h>
#include <math.h>
#include <stdint.h>

#define N_ROWS      4096
#define NUM_CLASSES 751
#define D_FEAT      2048
#define MARGIN1     0.5f
#define NTILE       32
#define NBLOCKS_TRI 528
#define KC          64                    // halfs per k-chunk (128 B/row)
#define CHUNKS      (D_FEAT / KC)         // 32
#define STAGES      3
#define LDH         72                    // padded smem row stride (halfs)
#define STAGE_HALFS (128 * LDH)           // 9216
#define STAGE_BYTES (STAGE_HALFS * 2)     // 18432
#define SMEM_BYTES  (2 * STAGES * STAGE_BYTES)  // 110592
#define FIN_BLOCKS  16
#define LREG        24                    // ceil(751/32)

// ---------------- device scratch ---------------------------------------------
__device__ __half   g_feat_h[(size_t)N_ROWS * D_FEAT];
__device__ float    g_sq[N_ROWS];
__device__ float    g_xrow[N_ROWS];
__device__ unsigned g_min_an[N_ROWS];
__device__ unsigned g_max_ap[N_ROWS];
__device__ float    g_acc;
__device__ unsigned g_done = 0;           // wraps FIN_BLOCKS-1 -> 0 each launch

// ---------------- PTX helpers -------------------------------------------------
__device__ __forceinline__ uint32_t smem_u32(const void* p) {
    uint32_t a;
    asm("{ .reg .u64 t; cvta.to.shared.u64 t, %1; cvt.u32.u64 %0, t; }"
        : "=r"(a) : "l"(p));
    return a;
}
__device__ __forceinline__ void cpasync16(uint32_t dst, const void* src) {
    asm volatile("cp.async.cg.shared.global [%0], [%1], 16;" :: "r"(dst), "l"(src));
}
__device__ __forceinline__ void ldmx4(uint32_t* r, uint32_t addr) {
    asm volatile("ldmatrix.sync.aligned.m8n8.x4.shared.b16 {%0,%1,%2,%3}, [%4];"
                 : "=r"(r[0]), "=r"(r[1]), "=r"(r[2]), "=r"(r[3]) : "r"(addr));
}
__device__ __forceinline__ void mma_f16_16x8x16(float* c, const uint32_t* a,
                                                const uint32_t* b) {
    asm volatile(
        "mma.sync.aligned.m16n8k16.row.col.f32.f16.f16.f32 "
        "{%0,%1,%2,%3}, {%4,%5,%6,%7}, {%8,%9}, {%0,%1,%2,%3};"
        : "+f"(c[0]), "+f"(c[1]), "+f"(c[2]), "+f"(c[3])
        : "r"(a[0]), "r"(a[1]), "r"(a[2]), "r"(a[3]), "r"(b[0]), "r"(b[1]));
}

// ---------------- block reduce (blockDim.x == 256) -----------------------------
__device__ __forceinline__ float blockReduceSum(float v) {
    __shared__ float red[8];
    __shared__ float bc;
    int lane = threadIdx.x & 31, wid = threadIdx.x >> 5;
    #pragma unroll
    for (int s = 16; s; s >>= 1) v += __shfl_xor_sync(0xffffffffu, v, s);
    if (lane == 0) red[wid] = v;
    __syncthreads();
    if (threadIdx.x == 0) {
        float r = 0.f;
        #pragma unroll
        for (int w = 0; w < 8; ++w) r += red[w];
        bc = r;
    }
    __syncthreads();
    return bc;
}

// ---------------- fused prep: sq + fp16 convert + xent + init ------------------
// 2 warps per row: grid 1024 x 256 (8 warps -> 4 rows)
__global__ void prep_kernel(const float* __restrict__ feat,
                            const float* __restrict__ logits,
                            const int*   __restrict__ targets) {
    const int tid  = threadIdx.x;
    const int lane = tid & 31;
    const int wid  = tid >> 5;
    const int rloc = wid >> 1;             // 0..3 row within block
    const int half = wid & 1;              // which half of the row
    const int row  = blockIdx.x * 4 + rloc;

    // ---- sq + convert: this warp handles 1024 floats (8 float4 per lane) ----
    const float4* f = reinterpret_cast<const float4*>(feat + (size_t)row * D_FEAT)
                      + half * 256;
    uint2* o = reinterpret_cast<uint2*>(g_feat_h + (size_t)row * D_FEAT) + half * 256;
    float s0 = 0.f, s1 = 0.f, s2 = 0.f, s3 = 0.f;
    #pragma unroll
    for (int it = 0; it < 2; ++it) {
        float4 v0 = f[lane + (it * 4 + 0) * 32];
        float4 v1 = f[lane + (it * 4 + 1) * 32];
        float4 v2 = f[lane + (it * 4 + 2) * 32];
        float4 v3 = f[lane + (it * 4 + 3) * 32];
        __half2 a0 = __floats2half2_rn(v0.x, v0.y), a1 = __floats2half2_rn(v0.z, v0.w);
        __half2 b0 = __floats2half2_rn(v1.x, v1.y), b1 = __floats2half2_rn(v1.z, v1.w);
        __half2 c0 = __floats2half2_rn(v2.x, v2.y), c1 = __floats2half2_rn(v2.z, v2.w);
        __half2 d0 = __floats2half2_rn(v3.x, v3.y), d1 = __floats2half2_rn(v3.z, v3.w);
        float2 ra0 = __half22float2(a0), ra1 = __half22float2(a1);
        float2 rb0 = __half22float2(b0), rb1 = __half22float2(b1);
        float2 rc0 = __half22float2(c0), rc1 = __half22float2(c1);
        float2 rd0 = __half22float2(d0), rd1 = __half22float2(d1);
        s0 += ra0.x * ra0.x + ra0.y * ra0.y + ra1.x * ra1.x + ra1.y * ra1.y;
        s1 += rb0.x * rb0.x + rb0.y * rb0.y + rb1.x * rb1.x + rb1.y * rb1.y;
        s2 += rc0.x * rc0.x + rc0.y * rc0.y + rc1.x * rc1.x + rc1.y * rc1.y;
        s3 += rd0.x * rd0.x + rd0.y * rd0.y + rd1.x * rd1.x + rd1.y * rd1.y;
        uint2 w;
        w.x = *reinterpret_cast<uint32_t*>(&a0); w.y = *reinterpret_cast<uint32_t*>(&a1);
        o[lane + (it * 4 + 0) * 32] = w;
        w.x = *reinterpret_cast<uint32_t*>(&b0); w.y = *reinterpret_cast<uint32_t*>(&b1);
        o[lane + (it * 4 + 1) * 32] = w;
        w.x = *reinterpret_cast<uint32_t*>(&c0); w.y = *reinterpret_cast<uint32_t*>(&c1);
        o[lane + (it * 4 + 2) * 32] = w;
        w.x = *reinterpret_cast<uint32_t*>(&d0); w.y = *reinterpret_cast<uint32_t*>(&d1);
        o[lane + (it * 4 + 3) * 32] = w;
    }
    float s = (s0 + s1) + (s2 + s3);
    #pragma unroll
    for (int sft = 16; sft; sft >>= 1) s += __shfl_xor_sync(0xffffffffu, s, sft);

    __shared__ float sqp[8];
    if (lane == 0) sqp[wid] = s;

    // ---- xent on the half==0 warp of each row (regs-resident logits) ----
    float xe = 0.f;
    if (half == 0) {
        const float* lr = logits + (size_t)row * NUM_CLASSES;
        float lv[LREG];
        #pragma unroll
        for (int k = 0; k < LREG; ++k) {
            const int c = lane + k * 32;
            lv[k] = (c < NUM_CLASSES) ? lr[c] : -1e30f;
        }
        float m = -1e30f;
        #pragma unroll
        for (int k = 0; k < LREG; ++k) m = fmaxf(m, lv[k]);
        #pragma unroll
        for (int sft = 16; sft; sft >>= 1)
            m = fmaxf(m, __shfl_xor_sync(0xffffffffu, m, sft));
        float es = 0.f;
        #pragma unroll
        for (int k = 0; k < LREG; ++k) {
            const int c = lane + k * 32;
            es += (c < NUM_CLASSES) ? expf(lv[k] - m) : 0.f;
        }
        #pragma unroll
        for (int sft = 16; sft; sft >>= 1)
            es += __shfl_xor_sync(0xffffffffu, es, sft);
        xe = m + logf(es) - lr[targets[row]];
    }

    __syncthreads();
    if (half == 0 && lane == 0) {
        g_sq[row]     = sqp[2 * rloc] + sqp[2 * rloc + 1];
        g_xrow[row]   = xe;
        g_min_an[row] = 0x7F800000u;
        g_max_ap[row] = 0u;
        if (row == 0) g_acc = 0.f;
    }
}

// ---------------- fp16 HMMA Gram GEMM + batch-hard mining ---------------------
__global__ __launch_bounds__(256, 2) void gemm_mine_hmma() {
    extern __shared__ __half sm[];
    const int tid  = threadIdx.x;
    const int lane = tid & 31;
    const int wid  = tid >> 5;
    const int wm   = wid >> 1;       // 0..3
    const int wn   = wid & 1;        // 0..1
    const int grp  = lane >> 2;      // 0..7
    const int tig  = lane & 3;       // 0..3

    int t = blockIdx.x, a = 0;
    while (t >= NTILE - a) { t -= NTILE - a; ++a; }
    const int b = a + t;
    const bool diag = (a == b);
    const int i0 = a * 128, j0 = b * 128;

    const int rw = tid >> 3;
    const int q  = tid & 7;
    const __half* pA = g_feat_h + (size_t)(i0 + rw) * D_FEAT + q * 8;
    const __half* pB = g_feat_h + (size_t)(j0 + rw) * D_FEAT + q * 8;
    const uint32_t base = smem_u32(sm);
    const uint32_t ldst = (uint32_t)(rw * LDH + q * 8) * 2;
    const uint32_t smA = base, smB = base + STAGES * STAGE_BYTES;

    const uint32_t aoff = (uint32_t)((wm * 32 + (lane & 15)) * LDH
                                     + ((lane >> 4) << 3)) * 2;
    const uint32_t boff = (uint32_t)((wn * 64 + ((lane >> 4) << 3) + (lane & 7)) * LDH
                                     + (((lane >> 3) & 1) << 3)) * 2;

    auto load_chunk = [&](int s, int c) {
        const __half* aa = pA + c * KC;
        const __half* bb = pB + c * KC;
        const uint32_t da = smA + s * STAGE_BYTES + ldst;
        const uint32_t db = smB + s * STAGE_BYTES + ldst;
        #pragma unroll
        for (int u = 0; u < 4; ++u) {
            cpasync16(da + u * (32 * LDH * 2), aa + (size_t)(u * 32) * D_FEAT);
            cpasync16(db + u * (32 * LDH * 2), bb + (size_t)(u * 32) * D_FEAT);
        }
        asm volatile("cp.async.commit_group;" ::: "memory");
    };

    float acc[2][8][4];
    #pragma unroll
    for (int mf = 0; mf < 2; ++mf)
        #pragma unroll
        for (int nf = 0; nf < 8; ++nf)
            #pragma unroll
            for (int r = 0; r < 4; ++r) acc[mf][nf][r] = 0.f;

    load_chunk(0, 0);
    load_chunk(1, 1);

    for (int c = 0; c < CHUNKS; ++c) {
        const int s = c % STAGES;
        asm volatile("cp.async.wait_group 1;" ::: "memory");
        __syncthreads();
        if (c + STAGES - 1 < CHUNKS)
            load_chunk((c + STAGES - 1) % STAGES, c + STAGES - 1);

        const uint32_t As = smA + s * STAGE_BYTES + aoff;
        const uint32_t Bs = smB + s * STAGE_BYTES + boff;

        #pragma unroll
        for (int k16 = 0; k16 < 4; ++k16) {
            const uint32_t kb = k16 * 32;   // 16 halfs
            uint32_t av[2][4], bv[8][2];
            ldmx4(av[0], As + kb);
            ldmx4(av[1], As + kb + 16 * LDH * 2);
            #pragma unroll
            for (int p = 0; p < 4; ++p) {
                uint32_t r[4];
                ldmx4(r, Bs + kb + p * (16 * LDH * 2));
                bv[2 * p][0]     = r[0];
                bv[2 * p][1]     = r[1];
                bv[2 * p + 1][0] = r[2];
                bv[2 * p + 1][1] = r[3];
            }
            #pragma unroll
            for (int mf = 0; mf < 2; ++mf)
                #pragma unroll
                for (int nf = 0; nf < 8; ++nf)
                    mma_f16_16x8x16(acc[mf][nf], av[mf], bv[nf]);
        }
    }

    // ---------------- epilogue: d^2 + batch-hard mining ----------------------
    __syncthreads();
    unsigned* rminS = (unsigned*)sm;
    unsigned* rmaxS = rminS + 128;
    unsigned* cminS = rminS + 256;
    if (tid < 128) {
        rminS[tid] = 0x7F800000u;
        rmaxS[tid] = 0u;
        cminS[tid] = 0x7F800000u;
    }
    __syncthreads();

    const int ib = i0 + wm * 32 + grp;
    const int jb = j0 + wn * 64 + 2 * tig;

    float sqj[8][2];
    #pragma unroll
    for (int nf = 0; nf < 8; ++nf) {
        sqj[nf][0] = __ldg(&g_sq[jb + nf * 8]);
        sqj[nf][1] = __ldg(&g_sq[jb + nf * 8 + 1]);
    }

    float cl[8][2];
    #pragma unroll
    for (int nf = 0; nf < 8; ++nf) { cl[nf][0] = 1e30f; cl[nf][1] = 1e30f; }

    #pragma unroll
    for (int mf = 0; mf < 2; ++mf) {
        const int iA = ib + mf * 16, iB = iA + 8;
        const float sq0 = __ldg(&g_sq[iA]);
        const float sq1 = __ldg(&g_sq[iB]);
        float rm0 = 1e30f, rm1 = 1e30f, rx0 = 0.f, rx1 = 0.f;
        #pragma unroll
        for (int nf = 0; nf < 8; ++nf) {
            #pragma unroll
            for (int p = 0; p < 2; ++p) {
                const int j = jb + nf * 8 + p;
                float d0 = fmaxf(sq0 + sqj[nf][p] - 2.f * acc[mf][nf][p],     0.f);
                float d1 = fmaxf(sq1 + sqj[nf][p] - 2.f * acc[mf][nf][2 + p], 0.f);
                if (diag) {
                    bool s0 = (iA >> 2) == (j >> 2);
                    bool s1 = (iB >> 2) == (j >> 2);
                    if (s0) rx0 = fmaxf(rx0, d0); else rm0 = fminf(rm0, d0);
                    if (s1) rx1 = fmaxf(rx1, d1); else rm1 = fminf(rm1, d1);
                } else {
                    rm0 = fminf(rm0, d0);
                    rm1 = fminf(rm1, d1);
                    cl[nf][p] = fminf(cl[nf][p], fminf(d0, d1));
                }
            }
        }
        #pragma unroll
        for (int sft = 1; sft <= 2; sft <<= 1) {
            rm0 = fminf(rm0, __shfl_xor_sync(0xffffffffu, rm0, sft));
            rm1 = fminf(rm1, __shfl_xor_sync(0xffffffffu, rm1, sft));
            rx0 = fmaxf(rx0, __shfl_xor_sync(0xffffffffu, rx0, sft));
            rx1 = fmaxf(rx1, __shfl_xor_sync(0xffffffffu, rx1, sft));
        }
        if (tig == 0) {
            atomicMin(&rminS[iA - i0], __float_as_uint(rm0));
            atomicMin(&rminS[iB - i0], __float_as_uint(rm1));
            if (diag) {
                atomicMax(&rmaxS[iA - i0], __float_as_uint(rx0));
                atomicMax(&rmaxS[iB - i0], __float_as_uint(rx1));
            }
        }
    }

    if (!diag) {
        #pragma unroll
        for (int nf = 0; nf < 8; ++nf)
            #pragma unroll
            for (int p = 0; p < 2; ++p) {
                float v = cl[nf][p];
                #pragma unroll
                for (int sft = 4; sft <= 16; sft <<= 1)
                    v = fminf(v, __shfl_xor_sync(0xffffffffu, v, sft));
                if (grp == 0)
                    atomicMin(&cminS[wn * 64 + nf * 8 + 2 * tig + p],
                              __float_as_uint(v));
            }
    }

    __syncthreads();
    if (tid < 128) {
        atomicMin(&g_min_an[i0 + tid], rminS[tid]);
        if (diag) atomicMax(&g_max_ap[i0 + tid], rmaxS[tid]);
        else      atomicMin(&g_min_an[j0 + tid], cminS[tid]);
    }
}

// ---------------- final scalar (parallel, last-block-writes) -------------------
__global__ void finalize_kernel(float* __restrict__ out) {
    const int i = blockIdx.x * 256 + threadIdx.x;
    float xs = g_xrow[i];
    float ap = sqrtf(fmaxf(__uint_as_float(g_max_ap[i]), 1e-12f));
    float an = sqrtf(fmaxf(__uint_as_float(g_min_an[i]), 1e-12f));
    float tot = blockReduceSum(xs + fmaxf(ap - an + MARGIN1, 0.f));
    if (threadIdx.x == 0) {
        atomicAdd(&g_acc, tot);
        __threadfence();
        unsigned old = atomicInc(&g_done, FIN_BLOCKS - 1);
        if (old == FIN_BLOCKS - 1)
            out[0] = g_acc / (float)N_ROWS;
    }
}

// ---------------- launch --------------------------------------------------------
extern "C" void kernel_launch(void* const* d_in, const int* in_sizes, int n_in,
                              void* d_out, int out_size) {
    const float* logits  = (const float*)d_in[0];
    const float* feat    = (const float*)d_in[1];
    const int*   targets = (const int*)d_in[2];
    float* out = (float*)d_out;

    cudaFuncSetAttribute(gemm_mine_hmma,
                         cudaFuncAttributeMaxDynamicSharedMemorySize, SMEM_BYTES);

    prep_kernel<<<1024, 256>>>(feat, logits, targets);
    gemm_mine_hmma<<<NBLOCKS_TRI, 256, SMEM_BYTES>>>();
    finalize_kernel<<<FIN_BLOCKS, 256>>>(out);
}